// round 4
// baseline (speedup 1.0000x reference)
#include <cuda_runtime.h>
#include <cuda_fp16.h>
#include <cstdint>

#define N_TOK   131072
#define N_E     1024
#define E_DIM   256
#define TM      128              // tokens per CTA
#define TN      64               // codes per N-tile
#define NTIL    (N_E / TN)       // 16
#define THREADS 256
#define TAU     0.25f            // near-tie threshold -> exact rescore

#define APAD    264              // padded row stride in halves (528B): conflict-free
#define ABYTES  (TM * APAD * 2)          // 67584
#define BBYTES  (TN * APAD * 2)          // 33792 per buffer

// ---- SMEM map (bytes) -------------------------------------------------------
#define SA_OFF    0
#define SB_OFF    ABYTES                  // two buffers: SB_OFF + {0,1}*BBYTES
#define SWN_OFF   (SB_OFF + 2 * BBYTES)   // 135168: 1024 f32
#define SIDX_OFF  (SWN_OFF + 4096)        // 139264: 128 int
#define SRED_OFF  (SIDX_OFF + 512)        // 139776: 3 arrays of 256
#define SM_TOTAL  (SRED_OFF + 3 * 256 * 4)// 142848

// ---- device scratch (no allocations allowed) --------------------------------
__device__ float                      d_wnorm[N_E];
__device__ unsigned int               d_counts[N_E];
__device__ __align__(16) __half       d_wh[N_E * E_DIM];   // fp16 codebook
__device__ int                        d_nflag;
__device__ int                        d_flags[N_TOK];
__device__ int                        d_flagidx[N_TOK];

// ---- base-ISA helpers --------------------------------------------------------
__device__ __forceinline__ uint32_t smem_u32_of(const void* p) {
    uint32_t a;
    asm("{ .reg .u64 t; cvta.to.shared.u64 t, %1; cvt.u32.u64 %0, t; }"
        : "=r"(a) : "l"(p));
    return a;
}
#define CP_ASYNC16(dst, src) \
    asm volatile("cp.async.cg.shared.global [%0], [%1], 16;" :: "r"(dst), "l"(src) : "memory")
#define CP_COMMIT() asm volatile("cp.async.commit_group;" ::: "memory")
#define CP_WAIT1()  asm volatile("cp.async.wait_group 1;" ::: "memory")
#define CP_WAIT0()  asm volatile("cp.async.wait_group 0;" ::: "memory")

__device__ __forceinline__ void mma16816(float* d, const uint32_t* a, const uint32_t* b) {
    asm volatile(
        "mma.sync.aligned.m16n8k16.row.col.f32.f16.f16.f32 "
        "{%0,%1,%2,%3}, {%4,%5,%6,%7}, {%8,%9}, {%0,%1,%2,%3};"
        : "+f"(d[0]), "+f"(d[1]), "+f"(d[2]), "+f"(d[3])
        : "r"(a[0]), "r"(a[1]), "r"(a[2]), "r"(a[3]), "r"(b[0]), "r"(b[1]));
}

// =============================================================================
// Kernel 0: wnorm (fp32) + fp16 codebook + zero counts/flag counter
// =============================================================================
__global__ void vq_prep_kernel(const float* __restrict__ w) {
    int row  = (blockIdx.x * blockDim.x + threadIdx.x) >> 5;
    int lane = threadIdx.x & 31;
    if (blockIdx.x == 0 && threadIdx.x == 0) d_nflag = 0;
    if (row >= N_E) return;
    const float4* r4 = reinterpret_cast<const float4*>(w + (size_t)row * E_DIM);
    __half2* wh2 = reinterpret_cast<__half2*>(d_wh + (size_t)row * E_DIM);
    float s = 0.0f;
    #pragma unroll
    for (int i = 0; i < 2; i++) {
        float4 v = r4[lane + 32 * i];
        s = fmaf(v.x, v.x, s); s = fmaf(v.y, v.y, s);
        s = fmaf(v.z, v.z, s); s = fmaf(v.w, v.w, s);
        wh2[2 * (lane + 32 * i) + 0] = __floats2half2_rn(v.x, v.y);
        wh2[2 * (lane + 32 * i) + 1] = __floats2half2_rn(v.z, v.w);
    }
    #pragma unroll
    for (int off = 16; off; off >>= 1) s += __shfl_xor_sync(0xffffffffu, s, off);
    if (lane == 0) { d_wnorm[row] = s; d_counts[row] = 0u; }
}

// =============================================================================
// Kernel 1: fp16 mma.sync scores -> (best, second) argmin -> flags -> z_q, counts
// grid = 1024 CTAs x 256 thr. Warp grid 4(M) x 2(N); warp tile 32x32.
// =============================================================================
__global__ __launch_bounds__(THREADS, 1)
void vq_main_mma(const float* __restrict__ z,
                 const float* __restrict__ w,
                 float* __restrict__ out) {
    extern __shared__ char smem[];
    const uint32_t sbase = smem_u32_of(smem);
    __half* sA     = reinterpret_cast<__half*>(smem + SA_OFF);
    float*  wn_s   = reinterpret_cast<float*>(smem + SWN_OFF);
    int*    sidx_s = reinterpret_cast<int*>(smem + SIDX_OFF);
    float*  red_v  = reinterpret_cast<float*>(smem + SRED_OFF);
    float*  red_v2 = red_v + 256;
    int*    red_i  = reinterpret_cast<int*>(red_v2 + 256);

    const int tid    = threadIdx.x;
    const int lane   = tid & 31;
    const int wid    = tid >> 5;
    const int warp_m = wid & 3;          // 0..3 -> 32-row slab
    const int warp_n = wid >> 2;         // 0..1 -> 32-col slab
    const int lq     = lane >> 2;        // 0..7
    const int lr2    = (lane & 3) * 2;   // 0,2,4,6
    const int t0     = blockIdx.x * TM;

    // ---- B tile 0 prefetch (cp.async) ------------------------------------
    auto loadB = [&](int tt) {
        const int n0 = tt * TN;
        const uint32_t dbase = sbase + SB_OFF + (uint32_t)(tt & 1) * BBYTES;
        const __half* src = d_wh + (size_t)n0 * E_DIM;
        #pragma unroll
        for (int i = 0; i < 8; i++) {
            int idx = tid + i * THREADS;       // 2048 16B chunks
            int r   = idx >> 5;                // code row 0..63
            int ch  = idx & 31;                // 16B chunk (8 halves)
            CP_ASYNC16(dbase + (uint32_t)r * (APAD * 2) + (uint32_t)ch * 16,
                       src + (size_t)r * E_DIM + ch * 8);
        }
    };
    loadB(0); CP_COMMIT();

    // ---- stage code norms --------------------------------------------------
    for (int i = tid; i < N_E; i += THREADS) wn_s[i] = d_wnorm[i];

    // ---- A: load z tile fp32, convert fp16 into padded SMEM ---------------
    {
        const float4* zb = reinterpret_cast<const float4*>(z + (size_t)t0 * E_DIM);
        #pragma unroll
        for (int i = 0; i < 32; i++) {
            int idx = tid + i * THREADS;       // 8192 float4
            int r   = idx >> 6;
            int c   = idx & 63;                // float4 col
            float4 v = zb[idx];
            __half2 h0 = __floats2half2_rn(v.x, v.y);
            __half2 h1 = __floats2half2_rn(v.z, v.w);
            uint2 p;
            p.x = *reinterpret_cast<uint32_t*>(&h0);
            p.y = *reinterpret_cast<uint32_t*>(&h1);
            *reinterpret_cast<uint2*>(
                reinterpret_cast<char*>(sA) + (size_t)r * (APAD * 2) + c * 8) = p;
        }
    }

    // ---- running per-lane argmin state (4 local rows) ----------------------
    float bv[4], bv2[4];
    int   bi[4];
    #pragma unroll
    for (int i = 0; i < 4; i++) { bv[i] = 3.4e38f; bv2[i] = 3.4e38f; bi[i] = 0; }

    const __half* Abase = sA + (size_t)(warp_m * 32 + lq) * APAD;

    for (int t = 0; t < NTIL; t++) {
        if (t + 1 < NTIL) { loadB(t + 1); CP_COMMIT(); CP_WAIT1(); }
        else              { CP_WAIT0(); }
        __syncthreads();

        const __half* Bt = reinterpret_cast<const __half*>(
            smem + SB_OFF + (size_t)(t & 1) * BBYTES);
        const __half* Bbase = Bt + (size_t)(warp_n * 32 + lq) * APAD;

        float acc[2][4][4];
        #pragma unroll
        for (int mf = 0; mf < 2; mf++)
            #pragma unroll
            for (int nf = 0; nf < 4; nf++)
                #pragma unroll
                for (int c = 0; c < 4; c++) acc[mf][nf][c] = 0.0f;

        #pragma unroll
        for (int k = 0; k < E_DIM; k += 16) {
            uint32_t a[2][4], b[4][2];
            #pragma unroll
            for (int mf = 0; mf < 2; mf++) {
                const __half* ap = Abase + (size_t)mf * 16 * APAD + k + lr2;
                a[mf][0] = *reinterpret_cast<const uint32_t*>(ap);
                a[mf][1] = *reinterpret_cast<const uint32_t*>(ap + 8 * APAD);
                a[mf][2] = *reinterpret_cast<const uint32_t*>(ap + 8);
                a[mf][3] = *reinterpret_cast<const uint32_t*>(ap + 8 * APAD + 8);
            }
            #pragma unroll
            for (int nf = 0; nf < 4; nf++) {
                const __half* bp = Bbase + (size_t)nf * 8 * APAD + k + lr2;
                b[nf][0] = *reinterpret_cast<const uint32_t*>(bp);
                b[nf][1] = *reinterpret_cast<const uint32_t*>(bp + 8);
            }
            #pragma unroll
            for (int mf = 0; mf < 2; mf++)
                #pragma unroll
                for (int nf = 0; nf < 4; nf++)
                    mma16816(acc[mf][nf], a[mf], b[nf]);
        }

        // fold: dist = ||w||^2 - 2*dot ; track best + second
        float wnv[8];
        #pragma unroll
        for (int nf = 0; nf < 4; nf++) {
            int nb = t * TN + warp_n * 32 + nf * 8 + lr2;
            wnv[nf * 2 + 0] = wn_s[nb + 0];
            wnv[nf * 2 + 1] = wn_s[nb + 1];
        }
        #pragma unroll
        for (int mf = 0; mf < 2; mf++) {
            #pragma unroll
            for (int r2 = 0; r2 < 2; r2++) {
                const int li = mf * 2 + r2;
                #pragma unroll
                for (int nf = 0; nf < 4; nf++) {
                    #pragma unroll
                    for (int c = 0; c < 2; c++) {
                        float dist = fmaf(-2.0f, acc[mf][nf][r2 * 2 + c],
                                          wnv[nf * 2 + c]);
                        int n = t * TN + warp_n * 32 + nf * 8 + lr2 + c;
                        if (dist < bv[li]) {
                            bv2[li] = bv[li]; bv[li] = dist; bi[li] = n;
                        } else if (dist < bv2[li]) {
                            bv2[li] = dist;
                        }
                    }
                }
            }
        }
        __syncthreads();   // all warps done with buf (t&1) before it's refilled
    }

    // ---- reduce across the 4 lanes of each quad (same rows, diff cols) ----
    #pragma unroll
    for (int off = 1; off <= 2; off <<= 1) {
        #pragma unroll
        for (int li = 0; li < 4; li++) {
            float ov  = __shfl_xor_sync(0xffffffffu, bv[li],  off);
            float ov2 = __shfl_xor_sync(0xffffffffu, bv2[li], off);
            int   oi  = __shfl_xor_sync(0xffffffffu, bi[li],  off);
            float nb2 = fminf(fmaxf(bv[li], ov), fminf(bv2[li], ov2));
            if (ov < bv[li] || (ov == bv[li] && oi < bi[li])) {
                bv[li] = ov; bi[li] = oi;
            }
            bv2[li] = nb2;
        }
    }
    if ((lane & 3) == 0) {
        #pragma unroll
        for (int li = 0; li < 4; li++) {
            int mf = li >> 1, r2 = li & 1;
            int row = warp_m * 32 + mf * 16 + lq + r2 * 8;   // 0..127
            red_v [row * 2 + warp_n] = bv[li];
            red_v2[row * 2 + warp_n] = bv2[li];
            red_i [row * 2 + warp_n] = bi[li];
        }
    }
    __syncthreads();

    // ---- final per-token merge (2 N-warp halves), counts, flags ------------
    if (tid < TM) {
        float v0 = red_v[tid * 2],     v1 = red_v[tid * 2 + 1];
        float s0 = red_v2[tid * 2],    s1 = red_v2[tid * 2 + 1];
        int   i0 = red_i[tid * 2],     i1 = red_i[tid * 2 + 1];
        float fb2 = fminf(fmaxf(v0, v1), fminf(s0, s1));
        float fb  = v0; int fi = i0;
        if (v1 < v0 || (v1 == v0 && i1 < i0)) { fb = v1; fi = i1; }
        sidx_s[tid] = fi;
        atomicAdd(&d_counts[fi], 1u);
        if (fb2 - fb < TAU) {
            int s = atomicAdd(&d_nflag, 1);
            d_flags[s]   = t0 + tid;
            d_flagidx[s] = fi;
        }
    }
    __syncthreads();

    // ---- z_q gather: exact fp32 codebook rows, coalesced -------------------
    #pragma unroll 4
    for (int i = 0; i < 32; i++) {
        int idx = i * THREADS + tid;          // 128 rows x 64 float4
        int r   = idx >> 6;
        int c4  = idx & 63;
        int ci  = sidx_s[r];
        float4 wv = reinterpret_cast<const float4*>(w + (size_t)ci * E_DIM)[c4];
        reinterpret_cast<float4*>(out + (size_t)(t0 + r) * E_DIM)[c4] = wv;
    }
}

// =============================================================================
// Kernel 2: exact fp32 rescore for near-tie tokens; patch out + counts
// =============================================================================
__global__ void vq_fallback(const float* __restrict__ z,
                            const float* __restrict__ w,
                            float* __restrict__ out) {
    __shared__ float zs[E_DIM];
    __shared__ float rv[256];
    __shared__ int   ri[256];
    __shared__ int   s_new;
    const int tid = threadIdx.x;
    const int nf  = *((volatile int*)&d_nflag);

    for (int f = blockIdx.x; f < nf; f += gridDim.x) {
        const int tok = d_flags[f];
        const int old = d_flagidx[f];
        __syncthreads();
        zs[tid] = z[(size_t)tok * E_DIM + tid];
        __syncthreads();

        float bd = 3.4e38f; int bidx = 0x7fffffff;
        for (int c = tid; c < N_E; c += 256) {
            const float* wr = w + (size_t)c * E_DIM;
            float s = 0.0f;
            #pragma unroll 8
            for (int k = 0; k < E_DIM; k++) s = fmaf(zs[k], wr[k], s);
            float dist = fmaf(-2.0f, s, d_wnorm[c]);
            if (dist < bd || (dist == bd && c < bidx)) { bd = dist; bidx = c; }
        }
        rv[tid] = bd; ri[tid] = bidx;
        __syncthreads();
        for (int st = 128; st > 0; st >>= 1) {
            if (tid < st) {
                float ov = rv[tid + st]; int oi = ri[tid + st];
                if (ov < rv[tid] || (ov == rv[tid] && oi < ri[tid])) {
                    rv[tid] = ov; ri[tid] = oi;
                }
            }
            __syncthreads();
        }
        if (tid == 0) {
            int nw = ri[0];
            if (nw != old) {
                atomicAdd(&d_counts[nw], 1u);
                atomicSub(&d_counts[old], 1u);
            }
            s_new = nw;
        }
        __syncthreads();
        out[(size_t)tok * E_DIM + tid] = w[(size_t)s_new * E_DIM + tid];
    }
}

// =============================================================================
// Kernel 3: perplexity
// =============================================================================
__global__ void vq_perplexity_kernel(float* __restrict__ out_perp) {
    __shared__ float red[N_E];
    int t = threadIdx.x;
    float e = (float)d_counts[t] * (1.0f / (float)N_TOK);
    red[t] = -e * logf(e + 1e-10f);
    __syncthreads();
    #pragma unroll
    for (int s = N_E / 2; s > 0; s >>= 1) {
        if (t < s) red[t] += red[t + s];
        __syncthreads();
    }
    if (t == 0) *out_perp = expf(red[0]);
}

// =============================================================================
extern "C" void kernel_launch(void* const* d_in, const int* in_sizes, int n_in,
                              void* d_out, int out_size) {
    const float* z = (const float*)d_in[0];   // [N_TOK, E_DIM]
    const float* w = (const float*)d_in[1];   // [N_E, E_DIM]
    float* out = (float*)d_out;

    cudaFuncSetAttribute(vq_main_mma,
                         cudaFuncAttributeMaxDynamicSharedMemorySize, SM_TOTAL);

    vq_prep_kernel<<<128, 256>>>(w);
    vq_main_mma<<<N_TOK / TM, THREADS, SM_TOTAL>>>(z, w, out);
    vq_fallback<<<256, 256>>>(z, w, out);
    if (out_size > N_TOK * E_DIM) {
        vq_perplexity_kernel<<<1, N_E>>>(out + (size_t)N_TOK * E_DIM);
    }
}

// round 6
// speedup vs baseline: 2.3105x; 2.3105x over previous
#include <cuda_runtime.h>
#include <cstdint>

#define N_TOK   131072
#define N_E     1024
#define E_DIM   256

#define TM      128      // tokens per block
#define TN      64       // codes per inner tile
#define NTILES  (N_E / TN)
#define PAD_K   260      // padded row stride (floats)
#define THREADS 512

__device__ float        d_wnorm[N_E];
__device__ unsigned int d_counts[N_E];

// packed fp32x2 FMA: d.lo += a.lo*b.lo ; d.hi += a.hi*b.hi  (SASS FFMA2)
__device__ __forceinline__ void ffma2(unsigned long long& acc,
                                      unsigned long long a,
                                      unsigned long long b) {
    asm("fma.rn.f32x2 %0, %1, %2, %0;" : "+l"(acc) : "l"(a), "l"(b));
}
__device__ __forceinline__ float fold2(unsigned long long acc) {
    float lo, hi;
    asm("mov.b64 {%0, %1}, %2;" : "=f"(lo), "=f"(hi) : "l"(acc));
    return lo + hi;
}

// ---------------------------------------------------------------------------
// Kernel 0: per-code squared norms + zero counts (graph-replay safe).
// ---------------------------------------------------------------------------
__global__ void vq_prep_kernel(const float* __restrict__ w) {
    int warp = (blockIdx.x * blockDim.x + threadIdx.x) >> 5;
    int lane = threadIdx.x & 31;
    if (warp < N_E) {
        const float4* row = reinterpret_cast<const float4*>(w + (size_t)warp * E_DIM);
        float s = 0.0f;
        #pragma unroll
        for (int i = 0; i < 2; i++) {
            float4 v = row[lane + 32 * i];
            s = fmaf(v.x, v.x, s);
            s = fmaf(v.y, v.y, s);
            s = fmaf(v.z, v.z, s);
            s = fmaf(v.w, v.w, s);
        }
        #pragma unroll
        for (int off = 16; off; off >>= 1)
            s += __shfl_xor_sync(0xffffffffu, s, off);
        if (lane == 0) {
            d_wnorm[warp]  = s;
            d_counts[warp] = 0u;
        }
    }
}

// ---------------------------------------------------------------------------
// Kernel 1: fused scores -> argmin -> z_q gather -> code counts.
// Same structure as the proven R1 kernel; inner product now uses packed
// fma.rn.f32x2 (FFMA2): acc.lo accumulates even-k, acc.hi odd-k, folded at
// the tile epilogue. Full fp32 precision, 2x FFMA throughput.
// ---------------------------------------------------------------------------
__global__ __launch_bounds__(THREADS, 1)
void vq_main_kernel(const float* __restrict__ z,
                    const float* __restrict__ w,
                    float* __restrict__ out) {
    extern __shared__ float sm[];
    float* zs   = sm;                                // [TM][PAD_K]
    float* ws   = zs + TM * PAD_K;                   // [TN][PAD_K]
    float* wn   = ws + TN * PAD_K;                   // [N_E]
    int*   sidx = reinterpret_cast<int*>(wn + N_E);  // [TM]

    const int tid = threadIdx.x;
    const int t0  = blockIdx.x * TM;

    // stage all 1024 code norms once
    for (int i = tid; i < N_E; i += THREADS) wn[i] = d_wnorm[i];

    // stage z tile [TM][E_DIM] row-major (coalesced float4, conflict-free STS)
    {
        const int kk    = (tid & 63) * 4;
        const int mbase = tid >> 6;          // 0..7
        #pragma unroll
        for (int it = 0; it < 16; it++) {
            int m = mbase + it * 8;
            float4 v = *reinterpret_cast<const float4*>(
                z + (size_t)(t0 + m) * E_DIM + kk);
            *reinterpret_cast<float4*>(zs + m * PAD_K + kk) = v;
        }
    }

    const int tx = tid & 15;    // code lane
    const int ty = tid >> 4;    // token lane (0..31)

    float bestv[4];
    int   besti[4];
    #pragma unroll
    for (int i = 0; i < 4; i++) { bestv[i] = 3.4e38f; besti[i] = 0x7fffffff; }

    for (int tile = 0; tile < NTILES; tile++) {
        const int c0 = tile * TN;

        __syncthreads();   // previous tile's ws fully consumed
        // stage w tile [TN][E_DIM]
        {
            const int kk    = (tid & 63) * 4;
            const int nbase = tid >> 6;
            #pragma unroll
            for (int it = 0; it < 8; it++) {
                int n = nbase + it * 8;
                float4 v = *reinterpret_cast<const float4*>(
                    w + (size_t)(c0 + n) * E_DIM + kk);
                *reinterpret_cast<float4*>(ws + n * PAD_K + kk) = v;
            }
        }
        __syncthreads();

        unsigned long long acc[4][4];
        #pragma unroll
        for (int i = 0; i < 4; i++)
            #pragma unroll
            for (int j = 0; j < 4; j++) acc[i][j] = 0ULL;

        #pragma unroll 4
        for (int k = 0; k < E_DIM; k += 4) {
            ulonglong2 a[4], b[4];
            #pragma unroll
            for (int i = 0; i < 4; i++)
                a[i] = *reinterpret_cast<const ulonglong2*>(zs + (ty + 32 * i) * PAD_K + k);
            #pragma unroll
            for (int j = 0; j < 4; j++)
                b[j] = *reinterpret_cast<const ulonglong2*>(ws + (tx + 16 * j) * PAD_K + k);
            #pragma unroll
            for (int i = 0; i < 4; i++) {
                #pragma unroll
                for (int j = 0; j < 4; j++) {
                    ffma2(acc[i][j], a[i].x, b[j].x);
                    ffma2(acc[i][j], a[i].y, b[j].y);
                }
            }
        }

        // fold tile into running argmin (tie -> lower index, like jnp.argmin)
        #pragma unroll
        for (int j = 0; j < 4; j++) {
            int   n   = c0 + tx + 16 * j;
            float wnv = wn[n];
            #pragma unroll
            for (int i = 0; i < 4; i++) {
                float dist = fmaf(-2.0f, fold2(acc[i][j]), wnv);
                if (dist < bestv[i] || (dist == bestv[i] && n < besti[i])) {
                    bestv[i] = dist;
                    besti[i] = n;
                }
            }
        }
    }

    // reduce argmin across the 16 code-lanes (stays inside a half-warp)
    #pragma unroll
    for (int off = 1; off < 16; off <<= 1) {
        #pragma unroll
        for (int i = 0; i < 4; i++) {
            float ov = __shfl_xor_sync(0xffffffffu, bestv[i], off);
            int   oi = __shfl_xor_sync(0xffffffffu, besti[i], off);
            if (ov < bestv[i] || (ov == bestv[i] && oi < besti[i])) {
                bestv[i] = ov;
                besti[i] = oi;
            }
        }
    }

    if (tx == 0) {
        #pragma unroll
        for (int i = 0; i < 4; i++) {
            int m = ty + 32 * i;
            sidx[m] = besti[i];
            atomicAdd(&d_counts[besti[i]], 1u);
        }
    }
    __syncthreads();

    // fused gather epilogue: out = w[idx] (== z + (w[idx]-z)), coalesced
    {
        const int kk    = (tid & 63) * 4;
        const int mbase = tid >> 6;
        #pragma unroll
        for (int it = 0; it < 16; it++) {
            int m  = mbase + it * 8;
            int ci = sidx[m];
            float4 wv = *reinterpret_cast<const float4*>(
                w + (size_t)ci * E_DIM + kk);
            *reinterpret_cast<float4*>(out + (size_t)(t0 + m) * E_DIM + kk) = wv;
        }
    }
}

// ---------------------------------------------------------------------------
// Kernel 2: perplexity = exp(-sum(e_mean * log(e_mean + 1e-10)))
// ---------------------------------------------------------------------------
__global__ void vq_perplexity_kernel(float* __restrict__ out_perp) {
    __shared__ float red[N_E];
    int t = threadIdx.x;
    float e    = (float)d_counts[t] * (1.0f / (float)N_TOK);
    red[t]     = -e * logf(e + 1e-10f);
    __syncthreads();
    #pragma unroll
    for (int s = N_E / 2; s > 0; s >>= 1) {
        if (t < s) red[t] += red[t + s];
        __syncthreads();
    }
    if (t == 0) *out_perp = expf(red[0]);
}

// ---------------------------------------------------------------------------
extern "C" void kernel_launch(void* const* d_in, const int* in_sizes, int n_in,
                              void* d_out, int out_size) {
    const float* z = (const float*)d_in[0];   // [N_TOK, E_DIM]
    const float* w = (const float*)d_in[1];   // [N_E, E_DIM]
    float* out = (float*)d_out;

    size_t smem_bytes = (size_t)(TM * PAD_K + TN * PAD_K + N_E) * sizeof(float)
                        + (size_t)TM * sizeof(int);
    cudaFuncSetAttribute(vq_main_kernel,
                         cudaFuncAttributeMaxDynamicSharedMemorySize,
                         (int)smem_bytes);

    vq_prep_kernel<<<128, 256>>>(w);
    vq_main_kernel<<<N_TOK / TM, THREADS, smem_bytes>>>(z, w, out);

    // output layout: z_q [N_TOK*E_DIM] followed by scalar perplexity
    if (out_size > N_TOK * E_DIM) {
        vq_perplexity_kernel<<<1, N_E>>>(out + (size_t)N_TOK * E_DIM);
    }
}

// round 8
// speedup vs baseline: 2.4031x; 1.0401x over previous
#include <cuda_runtime.h>
#include <cuda_fp16.h>
#include <cstdint>

#define N_TOK   131072
#define N_E     1024
#define E_DIM   256

#define TM      128      // tokens per block
#define TN      64       // codes per inner tile
#define NTILES  (N_E / TN)      // 16
#define THREADS 512
#define TAU     0.75f    // near-tie threshold -> exact rescore

#define BSTR    528      // SMEM row stride bytes (264 halves), mult of 16

// ---- SMEM map (bytes), main kernel ------------------------------------------
#define SA_OFF    0                               // z tile: 128*528 = 67584
#define SB_OFF    (TM * BSTR)                     // two buffers of 64*528
#define SWN_OFF   (SB_OFF + 2 * TN * BSTR)        // 135168
#define SIDX_OFF  (SWN_OFF + 4096)                // 139264
#define SM_TOTAL  (SIDX_OFF + 512)                // 139776

// ---- device scratch ----------------------------------------------------------
__device__ float                      d_wnorm[N_E];
__device__ unsigned int               d_counts[N_E];
__device__ __align__(16) __half       d_wh[N_E * E_DIM];   // fp16 codebook
__device__ int                        d_nflag;
__device__ int                        d_flags[N_TOK];
__device__ int                        d_flagidx[N_TOK];

// ---- helpers -------------------------------------------------------------------
__device__ __forceinline__ uint32_t smem_u32_of(const void* p) {
    uint32_t a;
    asm("{ .reg .u64 t; cvta.to.shared.u64 t, %1; cvt.u32.u64 %0, t; }"
        : "=r"(a) : "l"(p));
    return a;
}
#define CP_ASYNC16(dst, src) \
    asm volatile("cp.async.cg.shared.global [%0], [%1], 16;" :: "r"(dst), "l"(src) : "memory")
#define CP_COMMIT() asm volatile("cp.async.commit_group;" ::: "memory")
#define CP_WAIT1()  asm volatile("cp.async.wait_group 1;" ::: "memory")
#define CP_WAIT0()  asm volatile("cp.async.wait_group 0;" ::: "memory")

// =============================================================================
// Kernel 0: wnorm (fp32) + fp16 codebook + zero counts/flag counter
// =============================================================================
__global__ void vq_prep_kernel(const float* __restrict__ w) {
    int row  = (blockIdx.x * blockDim.x + threadIdx.x) >> 5;
    int lane = threadIdx.x & 31;
    if (blockIdx.x == 0 && threadIdx.x == 0) d_nflag = 0;
    if (row >= N_E) return;
    const float4* r4 = reinterpret_cast<const float4*>(w + (size_t)row * E_DIM);
    __half2* wh2 = reinterpret_cast<__half2*>(d_wh + (size_t)row * E_DIM);
    float s = 0.0f;
    #pragma unroll
    for (int i = 0; i < 2; i++) {
        float4 v = r4[lane + 32 * i];
        s = fmaf(v.x, v.x, s); s = fmaf(v.y, v.y, s);
        s = fmaf(v.z, v.z, s); s = fmaf(v.w, v.w, s);
        wh2[2 * (lane + 32 * i) + 0] = __floats2half2_rn(v.x, v.y);
        wh2[2 * (lane + 32 * i) + 1] = __floats2half2_rn(v.z, v.w);
    }
    #pragma unroll
    for (int off = 16; off; off >>= 1) s += __shfl_xor_sync(0xffffffffu, s, off);
    if (lane == 0) { d_wnorm[row] = s; d_counts[row] = 0u; }
}

// =============================================================================
// Kernel 1: HFMA2 scores (fold->fp32 every 32 k; 8 chunks cover all 256 k)
//           -> best/second argmin -> flags -> z_q gather, counts.
// 512 thr, tx=tid&15 (codes), ty=tid>>4 (tokens), micro-tile 4x4.
// =============================================================================
__global__ __launch_bounds__(THREADS, 1)
void vq_main_h2(const float* __restrict__ z,
                const float* __restrict__ w,
                float* __restrict__ out) {
    extern __shared__ char smem[];
    const uint32_t sbase = smem_u32_of(smem);
    float* wn_s   = reinterpret_cast<float*>(smem + SWN_OFF);
    int*   sidx_s = reinterpret_cast<int*>(smem + SIDX_OFF);

    const int tid = threadIdx.x;
    const int tx  = tid & 15;
    const int ty  = tid >> 4;
    const int t0  = blockIdx.x * TM;

    // ---- B tile loader: FULL rows (32 x 16B chunks per 64 rows) -------------
    auto loadB = [&](int tt) {
        const int n0 = tt * TN;
        const uint32_t dbase = sbase + SB_OFF + (uint32_t)(tt & 1) * (TN * BSTR);
        #pragma unroll
        for (int i = 0; i < 4; i++) {
            int idx = tid + i * THREADS;        // 2048 chunks = 64 rows x 32
            int r   = idx >> 5;
            int ch  = idx & 31;
            CP_ASYNC16(dbase + (uint32_t)r * BSTR + (uint32_t)ch * 16,
                       d_wh + (size_t)(n0 + r) * E_DIM + ch * 8);
        }
    };
    loadB(0); CP_COMMIT();

    // ---- stage code norms ------------------------------------------------------
    for (int i = tid; i < N_E; i += THREADS) wn_s[i] = d_wnorm[i];

    // ---- stage z tile: fp32 -> half2, rows stride 528 --------------------------
    {
        const float4* zb = reinterpret_cast<const float4*>(z + (size_t)t0 * E_DIM);
        #pragma unroll
        for (int i = 0; i < 16; i++) {
            int idx = tid + i * THREADS;        // 8192 float4
            int r   = idx >> 6;
            int c4  = idx & 63;
            float4 v = zb[idx];
            __half2 h0 = __floats2half2_rn(v.x, v.y);
            __half2 h1 = __floats2half2_rn(v.z, v.w);
            uint2 p;
            p.x = *reinterpret_cast<uint32_t*>(&h0);
            p.y = *reinterpret_cast<uint32_t*>(&h1);
            *reinterpret_cast<uint2*>(smem + SA_OFF + (size_t)r * BSTR + c4 * 8) = p;
        }
    }

    float bv[4], bv2[4];
    int   bi[4];
    #pragma unroll
    for (int i = 0; i < 4; i++) { bv[i] = 3.4e38f; bv2[i] = 3.4e38f; bi[i] = 0; }

    const char* za = smem + SA_OFF + (size_t)ty * BSTR;   // + i*32*BSTR

    for (int t = 0; t < NTILES; t++) {
        if (t + 1 < NTILES) { loadB(t + 1); CP_COMMIT(); CP_WAIT1(); }
        else                { CP_WAIT0(); }
        __syncthreads();    // tile t visible to all; prev reads of this buf done

        const char* wb = smem + SB_OFF + (size_t)(t & 1) * (TN * BSTR)
                         + (size_t)tx * BSTR;              // + j*16*BSTR

        float facc[4][4];
        #pragma unroll
        for (int i = 0; i < 4; i++)
            #pragma unroll
            for (int j = 0; j < 4; j++) facc[i][j] = 0.0f;

        #pragma unroll
        for (int kb = 0; kb < 8; kb++) {           // 8 chunks of 32 k = 256 k
            __half2 hacc[4][4];
            #pragma unroll
            for (int i = 0; i < 4; i++)
                #pragma unroll
                for (int j = 0; j < 4; j++) hacc[i][j] = __float2half2_rn(0.0f);

            #pragma unroll
            for (int kq = 0; kq < 8; kq++) {       // k4 steps (4 halves each)
                const int koff = kb * 64 + kq * 8; // bytes within row
                uint2 a[4], b[4];
                #pragma unroll
                for (int i = 0; i < 4; i++)
                    a[i] = *reinterpret_cast<const uint2*>(za + (size_t)i * (32 * BSTR) + koff);
                #pragma unroll
                for (int j = 0; j < 4; j++)
                    b[j] = *reinterpret_cast<const uint2*>(wb + (size_t)j * (16 * BSTR) + koff);
                #pragma unroll
                for (int i = 0; i < 4; i++) {
                    #pragma unroll
                    for (int j = 0; j < 4; j++) {
                        hacc[i][j] = __hfma2(*reinterpret_cast<__half2*>(&a[i].x),
                                             *reinterpret_cast<__half2*>(&b[j].x), hacc[i][j]);
                        hacc[i][j] = __hfma2(*reinterpret_cast<__half2*>(&a[i].y),
                                             *reinterpret_cast<__half2*>(&b[j].y), hacc[i][j]);
                    }
                }
            }
            // fold chunk into fp32
            #pragma unroll
            for (int i = 0; i < 4; i++)
                #pragma unroll
                for (int j = 0; j < 4; j++) {
                    float2 f = __half22float2(hacc[i][j]);
                    facc[i][j] += f.x + f.y;
                }
        }

        // dist = ||w||^2 - 2*dot ; keep best + second
        #pragma unroll
        for (int j = 0; j < 4; j++) {
            const int   n   = t * TN + tx + 16 * j;
            const float wnv = wn_s[n];
            #pragma unroll
            for (int i = 0; i < 4; i++) {
                float dist = fmaf(-2.0f, facc[i][j], wnv);
                if (dist < bv[i])       { bv2[i] = bv[i]; bv[i] = dist; bi[i] = n; }
                else if (dist < bv2[i]) { bv2[i] = dist; }
            }
        }
        __syncthreads();   // all reads of buf (t&1) done before refill
    }

    // ---- reduce best/second across the 16 code lanes (half-warp) ------------
    #pragma unroll
    for (int off = 1; off < 16; off <<= 1) {
        #pragma unroll
        for (int i = 0; i < 4; i++) {
            float ov  = __shfl_xor_sync(0xffffffffu, bv[i],  off);
            float ov2 = __shfl_xor_sync(0xffffffffu, bv2[i], off);
            int   oi  = __shfl_xor_sync(0xffffffffu, bi[i],  off);
            float nb2 = fminf(fmaxf(bv[i], ov), fminf(bv2[i], ov2));
            if (ov < bv[i] || (ov == bv[i] && oi < bi[i])) { bv[i] = ov; bi[i] = oi; }
            bv2[i] = nb2;
        }
    }
    if (tx == 0) {
        #pragma unroll
        for (int i = 0; i < 4; i++) {
            int m = ty + 32 * i;
            sidx_s[m] = bi[i];
            atomicAdd(&d_counts[bi[i]], 1u);
            if (bv2[i] - bv[i] < TAU) {
                int s = atomicAdd(&d_nflag, 1);
                d_flags[s]   = t0 + m;
                d_flagidx[s] = bi[i];
            }
        }
    }
    __syncthreads();

    // ---- z_q gather: exact fp32 codebook rows --------------------------------
    #pragma unroll 4
    for (int i = 0; i < 16; i++) {
        int idx = i * THREADS + tid;            // 128 rows x 64 float4
        int r   = idx >> 6;
        int c4  = idx & 63;
        int ci  = sidx_s[r];
        float4 wv = reinterpret_cast<const float4*>(w + (size_t)ci * E_DIM)[c4];
        reinterpret_cast<float4*>(out + (size_t)(t0 + r) * E_DIM)[c4] = wv;
    }
}

// =============================================================================
// Kernel 2: exact fp32 blocked rescore of flagged tokens, chunks of 32.
// 256 thr: tx=tid&15 (codes), ty=tid>>4 (tokens: rows ty, ty+16). micro 2x4.
// =============================================================================
#define FSTR  260                               // f32 row stride (floats)
#define FB_Z  0                                 // 32 * 1040 = 33280
#define FB_W  (32 * FSTR * 4)                   // 64 * 1040 = 66560
#define FB_WN (FB_W + 64 * FSTR * 4)            // 99840
#define FB_RI (FB_WN + 4096)                    // 103936
#define FB_SM (FB_RI + 128)                     // 104064

__global__ __launch_bounds__(256, 1)
void vq_fallback(const float* __restrict__ z,
                 const float* __restrict__ w,
                 float* __restrict__ out) {
    extern __shared__ char smem[];
    float* zf   = reinterpret_cast<float*>(smem + FB_Z);
    float* wf   = reinterpret_cast<float*>(smem + FB_W);
    float* wn_s = reinterpret_cast<float*>(smem + FB_WN);
    int*   ri_s = reinterpret_cast<int*>(smem + FB_RI);

    const int tid = threadIdx.x;
    const int tx  = tid & 15;
    const int ty  = tid >> 4;
    const int nf  = d_nflag;
    const int nchunks = (nf + 31) >> 5;

    for (int i = tid; i < N_E; i += 256) wn_s[i] = d_wnorm[i];

    for (int ch = blockIdx.x; ch < nchunks; ch += gridDim.x) {
        const int base = ch * 32;
        const int cnt  = min(32, nf - base);
        __syncthreads();

        // stage flagged z rows (invalid slots mirror slot 0)
        #pragma unroll
        for (int i = 0; i < 8; i++) {
            int idx = tid + i * 256;            // 32 x 64 float4
            int s   = idx >> 6;
            int c4  = idx & 63;
            int tok = d_flags[base + ((s < cnt) ? s : 0)];
            float4 v = reinterpret_cast<const float4*>(z + (size_t)tok * E_DIM)[c4];
            float* dst = zf + (size_t)s * FSTR + c4 * 4;
            dst[0] = v.x; dst[1] = v.y; dst[2] = v.z; dst[3] = v.w;
        }

        float bvf[2]; int bif[2];
        #pragma unroll
        for (int i = 0; i < 2; i++) { bvf[i] = 3.4e38f; bif[i] = 0x7fffffff; }

        for (int t = 0; t < 16; t++) {
            const int c0 = t * 64;
            __syncthreads();
            #pragma unroll
            for (int i = 0; i < 16; i++) {
                int idx = tid + i * 256;        // 64 x 64 float4
                int r   = idx >> 6;
                int c4  = idx & 63;
                float4 v = reinterpret_cast<const float4*>(w + (size_t)(c0 + r) * E_DIM)[c4];
                float* dst = wf + (size_t)r * FSTR + c4 * 4;
                dst[0] = v.x; dst[1] = v.y; dst[2] = v.z; dst[3] = v.w;
            }
            __syncthreads();

            float acc[2][4];
            #pragma unroll
            for (int i = 0; i < 2; i++)
                #pragma unroll
                for (int j = 0; j < 4; j++) acc[i][j] = 0.0f;

            #pragma unroll 4
            for (int k = 0; k < E_DIM; k += 4) {
                float4 a[2], b[4];
                #pragma unroll
                for (int i = 0; i < 2; i++)
                    a[i] = *reinterpret_cast<const float4*>(zf + (size_t)(ty + 16 * i) * FSTR + k);
                #pragma unroll
                for (int j = 0; j < 4; j++)
                    b[j] = *reinterpret_cast<const float4*>(wf + (size_t)(tx + 16 * j) * FSTR + k);
                #pragma unroll
                for (int i = 0; i < 2; i++)
                    #pragma unroll
                    for (int j = 0; j < 4; j++) {
                        acc[i][j] = fmaf(a[i].x, b[j].x, acc[i][j]);
                        acc[i][j] = fmaf(a[i].y, b[j].y, acc[i][j]);
                        acc[i][j] = fmaf(a[i].z, b[j].z, acc[i][j]);
                        acc[i][j] = fmaf(a[i].w, b[j].w, acc[i][j]);
                    }
            }
            #pragma unroll
            for (int j = 0; j < 4; j++) {
                int n = c0 + tx + 16 * j;
                float wnv = wn_s[n];
                #pragma unroll
                for (int i = 0; i < 2; i++) {
                    float dist = fmaf(-2.0f, acc[i][j], wnv);
                    if (dist < bvf[i] || (dist == bvf[i] && n < bif[i])) {
                        bvf[i] = dist; bif[i] = n;
                    }
                }
            }
        }

        // reduce across the 16 code lanes
        #pragma unroll
        for (int off = 1; off < 16; off <<= 1) {
            #pragma unroll
            for (int i = 0; i < 2; i++) {
                float ov = __shfl_xor_sync(0xffffffffu, bvf[i], off);
                int   oi = __shfl_xor_sync(0xffffffffu, bif[i], off);
                if (ov < bvf[i] || (ov == bvf[i] && oi < bif[i])) {
                    bvf[i] = ov; bif[i] = oi;
                }
            }
        }
        if (tx == 0) { ri_s[ty] = bif[0]; ri_s[ty + 16] = bif[1]; }
        __syncthreads();

        if (tid < cnt) {
            int nw  = ri_s[tid];
            int old = d_flagidx[base + tid];
            if (nw != old) {
                atomicAdd(&d_counts[nw], 1u);
                atomicSub(&d_counts[old], 1u);
            }
        }
        #pragma unroll
        for (int i = 0; i < 8; i++) {
            int idx = tid + i * 256;
            int s   = idx >> 6;
            int c4  = idx & 63;
            if (s < cnt) {
                int tok = d_flags[base + s];
                int ci  = ri_s[s];
                float4 wv = reinterpret_cast<const float4*>(w + (size_t)ci * E_DIM)[c4];
                reinterpret_cast<float4*>(out + (size_t)tok * E_DIM)[c4] = wv;
            }
        }
    }
}

// =============================================================================
// Kernel 3: perplexity
// =============================================================================
__global__ void vq_perplexity_kernel(float* __restrict__ out_perp) {
    __shared__ float red[N_E];
    int t = threadIdx.x;
    float e = (float)d_counts[t] * (1.0f / (float)N_TOK);
    red[t] = -e * logf(e + 1e-10f);
    __syncthreads();
    #pragma unroll
    for (int s = N_E / 2; s > 0; s >>= 1) {
        if (t < s) red[t] += red[t + s];
        __syncthreads();
    }
    if (t == 0) *out_perp = expf(red[0]);
}

// =============================================================================
extern "C" void kernel_launch(void* const* d_in, const int* in_sizes, int n_in,
                              void* d_out, int out_size) {
    const float* z = (const float*)d_in[0];   // [N_TOK, E_DIM]
    const float* w = (const float*)d_in[1];   // [N_E, E_DIM]
    float* out = (float*)d_out;

    cudaFuncSetAttribute(vq_main_h2,
                         cudaFuncAttributeMaxDynamicSharedMemorySize, SM_TOTAL);
    cudaFuncSetAttribute(vq_fallback,
                         cudaFuncAttributeMaxDynamicSharedMemorySize, FB_SM);

    vq_prep_kernel<<<128, 256>>>(w);
    vq_main_h2<<<N_TOK / TM, THREADS, SM_TOTAL>>>(z, w, out);
    vq_fallback<<<512, 256, FB_SM>>>(z, w, out);
    if (out_size > N_TOK * E_DIM) {
        vq_perplexity_kernel<<<1, N_E>>>(out + (size_t)N_TOK * E_DIM);
    }
}

// round 9
// speedup vs baseline: 2.4671x; 1.0266x over previous
#include <cuda_runtime.h>
#include <cuda_fp16.h>
#include <cstdint>

#define N_TOK   131072
#define N_E     1024
#define E_DIM   256

#define TM      128      // tokens per block
#define TN      64       // codes per inner tile
#define NTILES  (N_E / TN)      // 16
#define THREADS 256
#define TAU     0.75f    // near-tie threshold -> exact rescore

#define BSTR    528      // SMEM row stride bytes (264 halves), mult of 16

// ---- SMEM map (bytes), main kernel ------------------------------------------
#define SA_OFF    0                               // z tile: 128*528 = 67584
#define SB_OFF    (TM * BSTR)                     // two buffers of 64*528
#define SWN_OFF   (SB_OFF + 2 * TN * BSTR)        // 135168
#define SIDX_OFF  (SWN_OFF + 4096)                // 139264
#define SM_TOTAL  (SIDX_OFF + 512)                // 139776

// ---- device scratch ----------------------------------------------------------
__device__ float                      d_wnorm[N_E];
__device__ unsigned int               d_counts[N_E];
__device__ __align__(16) __half       d_wh[N_E * E_DIM];   // fp16 codebook
__device__ int                        d_nflag;
__device__ int                        d_flags[N_TOK];
__device__ int                        d_flagidx[N_TOK];

// ---- helpers -------------------------------------------------------------------
__device__ __forceinline__ uint32_t smem_u32_of(const void* p) {
    uint32_t a;
    asm("{ .reg .u64 t; cvta.to.shared.u64 t, %1; cvt.u32.u64 %0, t; }"
        : "=r"(a) : "l"(p));
    return a;
}
#define CP_ASYNC16(dst, src) \
    asm volatile("cp.async.cg.shared.global [%0], [%1], 16;" :: "r"(dst), "l"(src) : "memory")
#define CP_COMMIT() asm volatile("cp.async.commit_group;" ::: "memory")
#define CP_WAIT1()  asm volatile("cp.async.wait_group 1;" ::: "memory")
#define CP_WAIT0()  asm volatile("cp.async.wait_group 0;" ::: "memory")

__device__ __forceinline__ void hfma2_(__half2& acc, uint32_t a, uint32_t b) {
    acc = __hfma2(*reinterpret_cast<__half2*>(&a),
                  *reinterpret_cast<__half2*>(&b), acc);
}

// =============================================================================
// Kernel 0: wnorm (fp32) + fp16 codebook + zero counts/flag counter
// =============================================================================
__global__ void vq_prep_kernel(const float* __restrict__ w) {
    int row  = (blockIdx.x * blockDim.x + threadIdx.x) >> 5;
    int lane = threadIdx.x & 31;
    if (blockIdx.x == 0 && threadIdx.x == 0) d_nflag = 0;
    if (row >= N_E) return;
    const float4* r4 = reinterpret_cast<const float4*>(w + (size_t)row * E_DIM);
    __half2* wh2 = reinterpret_cast<__half2*>(d_wh + (size_t)row * E_DIM);
    float s = 0.0f;
    #pragma unroll
    for (int i = 0; i < 2; i++) {
        float4 v = r4[lane + 32 * i];
        s = fmaf(v.x, v.x, s); s = fmaf(v.y, v.y, s);
        s = fmaf(v.z, v.z, s); s = fmaf(v.w, v.w, s);
        wh2[2 * (lane + 32 * i) + 0] = __floats2half2_rn(v.x, v.y);
        wh2[2 * (lane + 32 * i) + 1] = __floats2half2_rn(v.z, v.w);
    }
    #pragma unroll
    for (int off = 16; off; off >>= 1) s += __shfl_xor_sync(0xffffffffu, s, off);
    if (lane == 0) { d_wnorm[row] = s; d_counts[row] = 0u; }
}

// =============================================================================
// Kernel 1: HFMA2 scores, micro-tile 8x4, uint4 LDS, fold->fp32 every 64 k.
// 256 thr: tx=tid&15 (codes tx+16j), ty=tid>>4 (token rows ty+16i, i<8).
// B tile stored with 16B XOR swizzle (ch ^ ((r>>3)&1)) to kill 2-way conflicts.
// =============================================================================
__global__ __launch_bounds__(THREADS, 1)
void vq_main_h2(const float* __restrict__ z,
                const float* __restrict__ w,
                float* __restrict__ out) {
    extern __shared__ char smem[];
    const uint32_t sbase = smem_u32_of(smem);
    float* wn_s   = reinterpret_cast<float*>(smem + SWN_OFF);
    int*   sidx_s = reinterpret_cast<int*>(smem + SIDX_OFF);

    const int tid = threadIdx.x;
    const int tx  = tid & 15;
    const int ty  = tid >> 4;
    const int t0  = blockIdx.x * TM;

    // ---- B tile loader: full 512B rows, 16B-XOR swizzled destinations --------
    auto loadB = [&](int tt) {
        const int n0 = tt * TN;
        const uint32_t dbase = sbase + SB_OFF + (uint32_t)(tt & 1) * (TN * BSTR);
        #pragma unroll
        for (int i = 0; i < 8; i++) {
            int idx = tid + i * THREADS;        // 2048 chunks = 64 rows x 32
            int r   = idx >> 5;
            int ch  = idx & 31;
            uint32_t col = ((uint32_t)ch * 16) ^ ((((uint32_t)r >> 3) & 1u) << 4);
            CP_ASYNC16(dbase + (uint32_t)r * BSTR + col,
                       d_wh + (size_t)(n0 + r) * E_DIM + ch * 8);
        }
    };
    loadB(0); CP_COMMIT();

    // ---- stage code norms ------------------------------------------------------
    for (int i = tid; i < N_E; i += THREADS) wn_s[i] = d_wnorm[i];

    // ---- stage z tile: fp32 -> half2, rows stride 528 (no swizzle) -------------
    {
        const float4* zb = reinterpret_cast<const float4*>(z + (size_t)t0 * E_DIM);
        #pragma unroll
        for (int i = 0; i < 32; i++) {
            int idx = tid + i * THREADS;        // 8192 float4
            int r   = idx >> 6;
            int c4  = idx & 63;
            float4 v = zb[idx];
            __half2 h0 = __floats2half2_rn(v.x, v.y);
            __half2 h1 = __floats2half2_rn(v.z, v.w);
            uint2 p;
            p.x = *reinterpret_cast<uint32_t*>(&h0);
            p.y = *reinterpret_cast<uint32_t*>(&h1);
            *reinterpret_cast<uint2*>(smem + SA_OFF + (size_t)r * BSTR + c4 * 8) = p;
        }
    }

    float bv[8], bv2[8];
    int   bi[8];
    #pragma unroll
    for (int i = 0; i < 8; i++) { bv[i] = 3.4e38f; bv2[i] = 3.4e38f; bi[i] = 0; }

    const char*    za  = smem + SA_OFF + (size_t)ty * BSTR;    // + i*16*BSTR
    const uint32_t bsw = (((uint32_t)tx >> 3) & 1u) << 4;      // B read swizzle

    for (int t = 0; t < NTILES; t++) {
        if (t + 1 < NTILES) { loadB(t + 1); CP_COMMIT(); CP_WAIT1(); }
        else                { CP_WAIT0(); }
        __syncthreads();    // tile t visible; prev reads of this buf done

        const char* wb = smem + SB_OFF + (size_t)(t & 1) * (TN * BSTR)
                         + (size_t)tx * BSTR;                  // + j*16*BSTR

        float facc[8][4];
        #pragma unroll
        for (int i = 0; i < 8; i++)
            #pragma unroll
            for (int j = 0; j < 4; j++) facc[i][j] = 0.0f;

        #pragma unroll
        for (int kb = 0; kb < 4; kb++) {            // 4 chunks of 64 k
            __half2 hacc[8][4];
            #pragma unroll
            for (int i = 0; i < 8; i++)
                #pragma unroll
                for (int j = 0; j < 4; j++) hacc[i][j] = __float2half2_rn(0.0f);

            #pragma unroll
            for (int kq = 0; kq < 8; kq++) {        // k8 steps (uint4 = 8 halves)
                const uint32_t koff = kb * 128 + kq * 16;   // bytes within row
                uint4 a[8], b[4];
                #pragma unroll
                for (int i = 0; i < 8; i++)
                    a[i] = *reinterpret_cast<const uint4*>(za + (size_t)i * (16 * BSTR) + koff);
                #pragma unroll
                for (int j = 0; j < 4; j++)
                    b[j] = *reinterpret_cast<const uint4*>(wb + (size_t)j * (16 * BSTR) + (koff ^ bsw));
                #pragma unroll
                for (int i = 0; i < 8; i++) {
                    #pragma unroll
                    for (int j = 0; j < 4; j++) {
                        hfma2_(hacc[i][j], a[i].x, b[j].x);
                        hfma2_(hacc[i][j], a[i].y, b[j].y);
                        hfma2_(hacc[i][j], a[i].z, b[j].z);
                        hfma2_(hacc[i][j], a[i].w, b[j].w);
                    }
                }
            }
            // fold chunk into fp32
            #pragma unroll
            for (int i = 0; i < 8; i++)
                #pragma unroll
                for (int j = 0; j < 4; j++) {
                    float2 f = __half22float2(hacc[i][j]);
                    facc[i][j] += f.x + f.y;
                }
        }

        // dist = ||w||^2 - 2*dot ; keep best + second
        #pragma unroll
        for (int j = 0; j < 4; j++) {
            const int   n   = t * TN + tx + 16 * j;
            const float wnv = wn_s[n];
            #pragma unroll
            for (int i = 0; i < 8; i++) {
                float dist = fmaf(-2.0f, facc[i][j], wnv);
                if (dist < bv[i])       { bv2[i] = bv[i]; bv[i] = dist; bi[i] = n; }
                else if (dist < bv2[i]) { bv2[i] = dist; }
            }
        }
        __syncthreads();   // all reads of buf (t&1) done before refill
    }

    // ---- reduce best/second across the 16 code lanes (xor 1..8 stays in ty) --
    #pragma unroll
    for (int off = 1; off < 16; off <<= 1) {
        #pragma unroll
        for (int i = 0; i < 8; i++) {
            float ov  = __shfl_xor_sync(0xffffffffu, bv[i],  off);
            float ov2 = __shfl_xor_sync(0xffffffffu, bv2[i], off);
            int   oi  = __shfl_xor_sync(0xffffffffu, bi[i],  off);
            float nb2 = fminf(fmaxf(bv[i], ov), fminf(bv2[i], ov2));
            if (ov < bv[i] || (ov == bv[i] && oi < bi[i])) { bv[i] = ov; bi[i] = oi; }
            bv2[i] = nb2;
        }
    }
    if (tx == 0) {
        #pragma unroll
        for (int i = 0; i < 8; i++) {
            int m = ty + 16 * i;
            sidx_s[m] = bi[i];
            atomicAdd(&d_counts[bi[i]], 1u);
            if (bv2[i] - bv[i] < TAU) {
                int s = atomicAdd(&d_nflag, 1);
                d_flags[s]   = t0 + m;
                d_flagidx[s] = bi[i];
            }
        }
    }
    __syncthreads();

    // ---- z_q gather: exact fp32 codebook rows --------------------------------
    #pragma unroll 4
    for (int i = 0; i < 32; i++) {
        int idx = i * THREADS + tid;            // 128 rows x 64 float4
        int r   = idx >> 6;
        int c4  = idx & 63;
        int ci  = sidx_s[r];
        float4 wv = reinterpret_cast<const float4*>(w + (size_t)ci * E_DIM)[c4];
        reinterpret_cast<float4*>(out + (size_t)(t0 + r) * E_DIM)[c4] = wv;
    }
}

// =============================================================================
// Kernel 2: exact fp32 blocked rescore of flagged tokens, chunks of 32.
// 256 thr: tx=tid&15 (codes), ty=tid>>4 (tokens: rows ty, ty+16). micro 2x4.
// =============================================================================
#define FSTR  260                               // f32 row stride (floats)
#define FB_Z  0
#define FB_W  (32 * FSTR * 4)
#define FB_WN (FB_W + 64 * FSTR * 4)
#define FB_RI (FB_WN + 4096)
#define FB_SM (FB_RI + 128)

__global__ __launch_bounds__(256, 1)
void vq_fallback(const float* __restrict__ z,
                 const float* __restrict__ w,
                 float* __restrict__ out) {
    extern __shared__ char smem[];
    float* zf   = reinterpret_cast<float*>(smem + FB_Z);
    float* wf   = reinterpret_cast<float*>(smem + FB_W);
    float* wn_s = reinterpret_cast<float*>(smem + FB_WN);
    int*   ri_s = reinterpret_cast<int*>(smem + FB_RI);

    const int tid = threadIdx.x;
    const int tx  = tid & 15;
    const int ty  = tid >> 4;
    const int nf  = d_nflag;
    const int nchunks = (nf + 31) >> 5;

    for (int i = tid; i < N_E; i += 256) wn_s[i] = d_wnorm[i];

    for (int ch = blockIdx.x; ch < nchunks; ch += gridDim.x) {
        const int base = ch * 32;
        const int cnt  = min(32, nf - base);
        __syncthreads();

        #pragma unroll
        for (int i = 0; i < 8; i++) {
            int idx = tid + i * 256;            // 32 x 64 float4
            int s   = idx >> 6;
            int c4  = idx & 63;
            int tok = d_flags[base + ((s < cnt) ? s : 0)];
            float4 v = reinterpret_cast<const float4*>(z + (size_t)tok * E_DIM)[c4];
            float* dst = zf + (size_t)s * FSTR + c4 * 4;
            dst[0] = v.x; dst[1] = v.y; dst[2] = v.z; dst[3] = v.w;
        }

        float bvf[2]; int bif[2];
        #pragma unroll
        for (int i = 0; i < 2; i++) { bvf[i] = 3.4e38f; bif[i] = 0x7fffffff; }

        for (int t = 0; t < 16; t++) {
            const int c0 = t * 64;
            __syncthreads();
            #pragma unroll
            for (int i = 0; i < 16; i++) {
                int idx = tid + i * 256;        // 64 x 64 float4
                int r   = idx >> 6;
                int c4  = idx & 63;
                float4 v = reinterpret_cast<const float4*>(w + (size_t)(c0 + r) * E_DIM)[c4];
                float* dst = wf + (size_t)r * FSTR + c4 * 4;
                dst[0] = v.x; dst[1] = v.y; dst[2] = v.z; dst[3] = v.w;
            }
            __syncthreads();

            float acc[2][4];
            #pragma unroll
            for (int i = 0; i < 2; i++)
                #pragma unroll
                for (int j = 0; j < 4; j++) acc[i][j] = 0.0f;

            #pragma unroll 4
            for (int k = 0; k < E_DIM; k += 4) {
                float4 a[2], b[4];
                #pragma unroll
                for (int i = 0; i < 2; i++)
                    a[i] = *reinterpret_cast<const float4*>(zf + (size_t)(ty + 16 * i) * FSTR + k);
                #pragma unroll
                for (int j = 0; j < 4; j++)
                    b[j] = *reinterpret_cast<const float4*>(wf + (size_t)(tx + 16 * j) * FSTR + k);
                #pragma unroll
                for (int i = 0; i < 2; i++)
                    #pragma unroll
                    for (int j = 0; j < 4; j++) {
                        acc[i][j] = fmaf(a[i].x, b[j].x, acc[i][j]);
                        acc[i][j] = fmaf(a[i].y, b[j].y, acc[i][j]);
                        acc[i][j] = fmaf(a[i].z, b[j].z, acc[i][j]);
                        acc[i][j] = fmaf(a[i].w, b[j].w, acc[i][j]);
                    }
            }
            #pragma unroll
            for (int j = 0; j < 4; j++) {
                int n = c0 + tx + 16 * j;
                float wnv = wn_s[n];
                #pragma unroll
                for (int i = 0; i < 2; i++) {
                    float dist = fmaf(-2.0f, acc[i][j], wnv);
                    if (dist < bvf[i] || (dist == bvf[i] && n < bif[i])) {
                        bvf[i] = dist; bif[i] = n;
                    }
                }
            }
        }

        #pragma unroll
        for (int off = 1; off < 16; off <<= 1) {
            #pragma unroll
            for (int i = 0; i < 2; i++) {
                float ov = __shfl_xor_sync(0xffffffffu, bvf[i], off);
                int   oi = __shfl_xor_sync(0xffffffffu, bif[i], off);
                if (ov < bvf[i] || (ov == bvf[i] && oi < bif[i])) {
                    bvf[i] = ov; bif[i] = oi;
                }
            }
        }
        if (tx == 0) { ri_s[ty] = bif[0]; ri_s[ty + 16] = bif[1]; }
        __syncthreads();

        if (tid < cnt) {
            int nw  = ri_s[tid];
            int old = d_flagidx[base + tid];
            if (nw != old) {
                atomicAdd(&d_counts[nw], 1u);
                atomicSub(&d_counts[old], 1u);
            }
        }
        #pragma unroll
        for (int i = 0; i < 8; i++) {
            int idx = tid + i * 256;
            int s   = idx >> 6;
            int c4  = idx & 63;
            if (s < cnt) {
                int tok = d_flags[base + s];
                int ci  = ri_s[s];
                float4 wv = reinterpret_cast<const float4*>(w + (size_t)ci * E_DIM)[c4];
                reinterpret_cast<float4*>(out + (size_t)tok * E_DIM)[c4] = wv;
            }
        }
    }
}

// =============================================================================
// Kernel 3: perplexity
// =============================================================================
__global__ void vq_perplexity_kernel(float* __restrict__ out_perp) {
    __shared__ float red[N_E];
    int t = threadIdx.x;
    float e = (float)d_counts[t] * (1.0f / (float)N_TOK);
    red[t] = -e * logf(e + 1e-10f);
    __syncthreads();
    #pragma unroll
    for (int s = N_E / 2; s > 0; s >>= 1) {
        if (t < s) red[t] += red[t + s];
        __syncthreads();
    }
    if (t == 0) *out_perp = expf(red[0]);
}

// =============================================================================
extern "C" void kernel_launch(void* const* d_in, const int* in_sizes, int n_in,
                              void* d_out, int out_size) {
    const float* z = (const float*)d_in[0];   // [N_TOK, E_DIM]
    const float* w = (const float*)d_in[1];   // [N_E, E_DIM]
    float* out = (float*)d_out;

    cudaFuncSetAttribute(vq_main_h2,
                         cudaFuncAttributeMaxDynamicSharedMemorySize, SM_TOTAL);
    cudaFuncSetAttribute(vq_fallback,
                         cudaFuncAttributeMaxDynamicSharedMemorySize, FB_SM);

    vq_prep_kernel<<<128, 256>>>(w);
    vq_main_h2<<<N_TOK / TM, THREADS, SM_TOTAL>>>(z, w, out);
    vq_fallback<<<512, 256, FB_SM>>>(z, w, out);
    if (out_size > N_TOK * E_DIM) {
        vq_perplexity_kernel<<<1, N_E>>>(out + (size_t)N_TOK * E_DIM);
    }
}

// round 10
// speedup vs baseline: 6.5043x; 2.6364x over previous
#include <cuda_runtime.h>
#include <cuda_fp16.h>
#include <cstdint>

#define N_TOK   131072
#define N_E     1024
#define E_DIM   256

#define TM      128      // tokens per block
#define TN      64       // codes per inner tile
#define NTILES  (N_E / TN)      // 16
#define THREADS 256
#define TAU     0.5f     // near-tie threshold -> exact rescore

#define BSTR    528      // SMEM row stride bytes (16B mult; 8rows x 16B -> all 32 banks)

// ---- SMEM map (bytes), main kernel ------------------------------------------
#define SA_OFF    0                               // z tile: 128*528 = 67584
#define SB_OFF    (TM * BSTR)                     // two buffers of 64*528
#define SWN_OFF   (SB_OFF + 2 * TN * BSTR)        // 135168: 1024 f32
#define SIDX_OFF  (SWN_OFF + 4096)                // 139264: 128 int
#define SRED_OFF  (SIDX_OFF + 512)                // 139776: 3 arrays of 256 f32/int
#define SM_TOTAL  (SRED_OFF + 3 * 256 * 4)        // 142848

// ---- device scratch ----------------------------------------------------------
__device__ float                      d_wnorm[N_E];
__device__ unsigned int               d_counts[N_E];
__device__ __align__(16) __half       d_wh[N_E * E_DIM];   // fp16 codebook
__device__ int                        d_nflag;
__device__ int                        d_flags[N_TOK];
__device__ int                        d_flagidx[N_TOK];

// ---- helpers -------------------------------------------------------------------
__device__ __forceinline__ uint32_t smem_u32_of(const void* p) {
    uint32_t a;
    asm("{ .reg .u64 t; cvta.to.shared.u64 t, %1; cvt.u32.u64 %0, t; }"
        : "=r"(a) : "l"(p));
    return a;
}
#define CP_ASYNC16(dst, src) \
    asm volatile("cp.async.cg.shared.global [%0], [%1], 16;" :: "r"(dst), "l"(src) : "memory")
#define CP_COMMIT() asm volatile("cp.async.commit_group;" ::: "memory")
#define CP_WAIT1()  asm volatile("cp.async.wait_group 1;" ::: "memory")
#define CP_WAIT0()  asm volatile("cp.async.wait_group 0;" ::: "memory")

__device__ __forceinline__ void ldsm_x4(uint32_t& r0, uint32_t& r1,
                                        uint32_t& r2, uint32_t& r3, uint32_t addr) {
    asm volatile("ldmatrix.sync.aligned.m8n8.x4.shared.b16 {%0,%1,%2,%3}, [%4];"
        : "=r"(r0), "=r"(r1), "=r"(r2), "=r"(r3) : "r"(addr));
}
__device__ __forceinline__ void mma16816(float* d, const uint32_t* a,
                                         uint32_t b0, uint32_t b1) {
    asm volatile(
        "mma.sync.aligned.m16n8k16.row.col.f32.f16.f16.f32 "
        "{%0,%1,%2,%3}, {%4,%5,%6,%7}, {%8,%9}, {%0,%1,%2,%3};"
        : "+f"(d[0]), "+f"(d[1]), "+f"(d[2]), "+f"(d[3])
        : "r"(a[0]), "r"(a[1]), "r"(a[2]), "r"(a[3]), "r"(b0), "r"(b1));
}

// =============================================================================
// Kernel 0: wnorm (fp32) + fp16 codebook + zero counts/flag counter
// =============================================================================
__global__ void vq_prep_kernel(const float* __restrict__ w) {
    int row  = (blockIdx.x * blockDim.x + threadIdx.x) >> 5;
    int lane = threadIdx.x & 31;
    if (blockIdx.x == 0 && threadIdx.x == 0) d_nflag = 0;
    if (row >= N_E) return;
    const float4* r4 = reinterpret_cast<const float4*>(w + (size_t)row * E_DIM);
    __half2* wh2 = reinterpret_cast<__half2*>(d_wh + (size_t)row * E_DIM);
    float s = 0.0f;
    #pragma unroll
    for (int i = 0; i < 2; i++) {
        float4 v = r4[lane + 32 * i];
        s = fmaf(v.x, v.x, s); s = fmaf(v.y, v.y, s);
        s = fmaf(v.z, v.z, s); s = fmaf(v.w, v.w, s);
        wh2[2 * (lane + 32 * i) + 0] = __floats2half2_rn(v.x, v.y);
        wh2[2 * (lane + 32 * i) + 1] = __floats2half2_rn(v.z, v.w);
    }
    #pragma unroll
    for (int off = 16; off; off >>= 1) s += __shfl_xor_sync(0xffffffffu, s, off);
    if (lane == 0) { d_wnorm[row] = s; d_counts[row] = 0u; }
}

// =============================================================================
// Kernel 1: ldmatrix + mma.sync(m16n8k16, f32 acc) scores -> best/second ->
//           flags -> z_q gather, counts.
// 256 thr = 8 warps: warp_m = wid&3 (32-row slab), warp_n = wid>>2 (32-col slab).
// Fragment <-> accumulator mapping identical to the R4 kernel (verified exact).
// =============================================================================
__global__ __launch_bounds__(THREADS, 1)
void vq_main_mma(const float* __restrict__ z,
                 const float* __restrict__ w,
                 float* __restrict__ out) {
    extern __shared__ char smem[];
    const uint32_t sbase = smem_u32_of(smem);
    float* wn_s   = reinterpret_cast<float*>(smem + SWN_OFF);
    int*   sidx_s = reinterpret_cast<int*>(smem + SIDX_OFF);
    float* red_v  = reinterpret_cast<float*>(smem + SRED_OFF);
    float* red_v2 = red_v + 256;
    int*   red_i  = reinterpret_cast<int*>(red_v2 + 256);

    const int tid    = threadIdx.x;
    const int lane   = tid & 31;
    const int wid    = tid >> 5;
    const int warp_m = wid & 3;
    const int warp_n = wid >> 2;
    const int lq     = lane >> 2;
    const int lr2    = (lane & 3) * 2;
    const int t0     = blockIdx.x * TM;

    // ---- B tile loader (cp.async, full 512B rows, stride 528) ---------------
    auto loadB = [&](int tt) {
        const int n0 = tt * TN;
        const uint32_t dbase = sbase + SB_OFF + (uint32_t)(tt & 1) * (TN * BSTR);
        #pragma unroll
        for (int i = 0; i < 8; i++) {
            int idx = tid + i * THREADS;        // 2048 chunks = 64 rows x 32
            int r   = idx >> 5;
            int ch  = idx & 31;
            CP_ASYNC16(dbase + (uint32_t)r * BSTR + (uint32_t)ch * 16,
                       d_wh + (size_t)(n0 + r) * E_DIM + ch * 8);
        }
    };
    loadB(0); CP_COMMIT();

    // ---- stage code norms ------------------------------------------------------
    for (int i = tid; i < N_E; i += THREADS) wn_s[i] = d_wnorm[i];

    // ---- stage z tile: fp32 -> half2, rows stride 528 ---------------------------
    {
        const float4* zb = reinterpret_cast<const float4*>(z + (size_t)t0 * E_DIM);
        #pragma unroll
        for (int i = 0; i < 32; i++) {
            int idx = tid + i * THREADS;        // 8192 float4
            int r   = idx >> 6;
            int c4  = idx & 63;
            float4 v = zb[idx];
            __half2 h0 = __floats2half2_rn(v.x, v.y);
            __half2 h1 = __floats2half2_rn(v.z, v.w);
            uint2 p;
            p.x = *reinterpret_cast<uint32_t*>(&h0);
            p.y = *reinterpret_cast<uint32_t*>(&h1);
            *reinterpret_cast<uint2*>(smem + SA_OFF + (size_t)r * BSTR + c4 * 8) = p;
        }
    }

    // ---- per-lane ldmatrix base addresses -----------------------------------
    // A x4: lanes 0-7/8-15 -> rows m..m+15 at col k; 16-23/24-31 same rows at k+8
    const uint32_t aBase = sbase + SA_OFF
        + (uint32_t)(warp_m * 32 + (lane & 15)) * BSTR + (uint32_t)(lane >> 4) * 16;
    // B x4: rows n..n+7 (M0,M1: cols k, k+8), rows n+8..n+15 (M2,M3)
    const uint32_t bRow = (uint32_t)((lane & 7) + ((lane >> 4) & 1) * 8) * BSTR
        + (uint32_t)((lane >> 3) & 1) * 16;

    float bv[4], bv2[4];
    int   bi[4];
    #pragma unroll
    for (int i = 0; i < 4; i++) { bv[i] = 3.4e38f; bv2[i] = 3.4e38f; bi[i] = 0; }

    for (int t = 0; t < NTILES; t++) {
        if (t + 1 < NTILES) { loadB(t + 1); CP_COMMIT(); CP_WAIT1(); }
        else                { CP_WAIT0(); }
        __syncthreads();

        const uint32_t bBase = sbase + SB_OFF + (uint32_t)(t & 1) * (TN * BSTR)
                             + (uint32_t)(warp_n * 32) * BSTR + bRow;

        float acc[2][4][4];
        #pragma unroll
        for (int mf = 0; mf < 2; mf++)
            #pragma unroll
            for (int nf = 0; nf < 4; nf++)
                #pragma unroll
                for (int c = 0; c < 4; c++) acc[mf][nf][c] = 0.0f;

        #pragma unroll
        for (int s = 0; s < 16; s++) {          // k16 steps, 256 total k
            const uint32_t kb = (uint32_t)s * 32;   // k bytes
            uint32_t a0[4], a1[4], b0[4], b1[4];
            ldsm_x4(a0[0], a0[1], a0[2], a0[3], aBase + kb);
            ldsm_x4(a1[0], a1[1], a1[2], a1[3], aBase + 16 * BSTR + kb);
            ldsm_x4(b0[0], b0[1], b0[2], b0[3], bBase + kb);
            ldsm_x4(b1[0], b1[1], b1[2], b1[3], bBase + 16 * BSTR + kb);
            mma16816(acc[0][0], a0, b0[0], b0[1]);
            mma16816(acc[0][1], a0, b0[2], b0[3]);
            mma16816(acc[0][2], a0, b1[0], b1[1]);
            mma16816(acc[0][3], a0, b1[2], b1[3]);
            mma16816(acc[1][0], a1, b0[0], b0[1]);
            mma16816(acc[1][1], a1, b0[2], b0[3]);
            mma16816(acc[1][2], a1, b1[0], b1[1]);
            mma16816(acc[1][3], a1, b1[2], b1[3]);
        }

        // fold: dist = ||w||^2 - 2*dot ; track best + second (R4-verified map)
        float wnv[8];
        #pragma unroll
        for (int nf = 0; nf < 4; nf++) {
            int nb = t * TN + warp_n * 32 + nf * 8 + lr2;
            wnv[nf * 2 + 0] = wn_s[nb + 0];
            wnv[nf * 2 + 1] = wn_s[nb + 1];
        }
        #pragma unroll
        for (int mf = 0; mf < 2; mf++) {
            #pragma unroll
            for (int r2 = 0; r2 < 2; r2++) {
                const int li = mf * 2 + r2;
                #pragma unroll
                for (int nf = 0; nf < 4; nf++) {
                    #pragma unroll
                    for (int c = 0; c < 2; c++) {
                        float dist = fmaf(-2.0f, acc[mf][nf][r2 * 2 + c],
                                          wnv[nf * 2 + c]);
                        int n = t * TN + warp_n * 32 + nf * 8 + lr2 + c;
                        if (dist < bv[li]) {
                            bv2[li] = bv[li]; bv[li] = dist; bi[li] = n;
                        } else if (dist < bv2[li]) {
                            bv2[li] = dist;
                        }
                    }
                }
            }
        }
        __syncthreads();   // all warps done with buf (t&1) before refill
    }

    // ---- reduce across the 4 lanes of each quad (same rows, diff cols) --------
    #pragma unroll
    for (int off = 1; off <= 2; off <<= 1) {
        #pragma unroll
        for (int li = 0; li < 4; li++) {
            float ov  = __shfl_xor_sync(0xffffffffu, bv[li],  off);
            float ov2 = __shfl_xor_sync(0xffffffffu, bv2[li], off);
            int   oi  = __shfl_xor_sync(0xffffffffu, bi[li],  off);
            float nb2 = fminf(fmaxf(bv[li], ov), fminf(bv2[li], ov2));
            if (ov < bv[li] || (ov == bv[li] && oi < bi[li])) {
                bv[li] = ov; bi[li] = oi;
            }
            bv2[li] = nb2;
        }
    }
    if ((lane & 3) == 0) {
        #pragma unroll
        for (int li = 0; li < 4; li++) {
            int mf = li >> 1, r2 = li & 1;
            int row = warp_m * 32 + mf * 16 + lq + r2 * 8;   // 0..127
            red_v [row * 2 + warp_n] = bv[li];
            red_v2[row * 2 + warp_n] = bv2[li];
            red_i [row * 2 + warp_n] = bi[li];
        }
    }
    __syncthreads();

    // ---- final per-token merge (2 N-warp halves), counts, flags ----------------
    if (tid < TM) {
        float v0 = red_v[tid * 2],  v1 = red_v[tid * 2 + 1];
        float s0 = red_v2[tid * 2], s1 = red_v2[tid * 2 + 1];
        int   i0 = red_i[tid * 2],  i1 = red_i[tid * 2 + 1];
        float fb2 = fminf(fmaxf(v0, v1), fminf(s0, s1));
        float fb  = v0; int fi = i0;
        if (v1 < v0 || (v1 == v0 && i1 < i0)) { fb = v1; fi = i1; }
        sidx_s[tid] = fi;
        atomicAdd(&d_counts[fi], 1u);
        if (fb2 - fb < TAU) {
            int s = atomicAdd(&d_nflag, 1);
            d_flags[s]   = t0 + tid;
            d_flagidx[s] = fi;
        }
    }
    __syncthreads();

    // ---- z_q gather: exact fp32 codebook rows ----------------------------------
    #pragma unroll 4
    for (int i = 0; i < 32; i++) {
        int idx = i * THREADS + tid;            // 128 rows x 64 float4
        int r   = idx >> 6;
        int c4  = idx & 63;
        int ci  = sidx_s[r];
        float4 wv = reinterpret_cast<const float4*>(w + (size_t)ci * E_DIM)[c4];
        reinterpret_cast<float4*>(out + (size_t)(t0 + r) * E_DIM)[c4] = wv;
    }
}

// =============================================================================
// Kernel 2: exact fp32 blocked rescore of flagged tokens, chunks of 32.
// =============================================================================
#define FSTR  260
#define FB_Z  0
#define FB_W  (32 * FSTR * 4)
#define FB_WN (FB_W + 64 * FSTR * 4)
#define FB_RI (FB_WN + 4096)
#define FB_SM (FB_RI + 128)

__global__ __launch_bounds__(256, 1)
void vq_fallback(const float* __restrict__ z,
                 const float* __restrict__ w,
                 float* __restrict__ out) {
    extern __shared__ char smem[];
    float* zf   = reinterpret_cast<float*>(smem + FB_Z);
    float* wf   = reinterpret_cast<float*>(smem + FB_W);
    float* wn_s = reinterpret_cast<float*>(smem + FB_WN);
    int*   ri_s = reinterpret_cast<int*>(smem + FB_RI);

    const int tid = threadIdx.x;
    const int tx  = tid & 15;
    const int ty  = tid >> 4;
    const int nf  = d_nflag;
    const int nchunks = (nf + 31) >> 5;

    for (int i = tid; i < N_E; i += 256) wn_s[i] = d_wnorm[i];

    for (int ch = blockIdx.x; ch < nchunks; ch += gridDim.x) {
        const int base = ch * 32;
        const int cnt  = min(32, nf - base);
        __syncthreads();

        #pragma unroll
        for (int i = 0; i < 8; i++) {
            int idx = tid + i * 256;
            int s   = idx >> 6;
            int c4  = idx & 63;
            int tok = d_flags[base + ((s < cnt) ? s : 0)];
            float4 v = reinterpret_cast<const float4*>(z + (size_t)tok * E_DIM)[c4];
            float* dst = zf + (size_t)s * FSTR + c4 * 4;
            dst[0] = v.x; dst[1] = v.y; dst[2] = v.z; dst[3] = v.w;
        }

        float bvf[2]; int bif[2];
        #pragma unroll
        for (int i = 0; i < 2; i++) { bvf[i] = 3.4e38f; bif[i] = 0x7fffffff; }

        for (int t = 0; t < 16; t++) {
            const int c0 = t * 64;
            __syncthreads();
            #pragma unroll
            for (int i = 0; i < 16; i++) {
                int idx = tid + i * 256;
                int r   = idx >> 6;
                int c4  = idx & 63;
                float4 v = reinterpret_cast<const float4*>(w + (size_t)(c0 + r) * E_DIM)[c4];
                float* dst = wf + (size_t)r * FSTR + c4 * 4;
                dst[0] = v.x; dst[1] = v.y; dst[2] = v.z; dst[3] = v.w;
            }
            __syncthreads();

            float acc[2][4];
            #pragma unroll
            for (int i = 0; i < 2; i++)
                #pragma unroll
                for (int j = 0; j < 4; j++) acc[i][j] = 0.0f;

            #pragma unroll 4
            for (int k = 0; k < E_DIM; k += 4) {
                float4 a[2], b[4];
                #pragma unroll
                for (int i = 0; i < 2; i++)
                    a[i] = *reinterpret_cast<const float4*>(zf + (size_t)(ty + 16 * i) * FSTR + k);
                #pragma unroll
                for (int j = 0; j < 4; j++)
                    b[j] = *reinterpret_cast<const float4*>(wf + (size_t)(tx + 16 * j) * FSTR + k);
                #pragma unroll
                for (int i = 0; i < 2; i++)
                    #pragma unroll
                    for (int j = 0; j < 4; j++) {
                        acc[i][j] = fmaf(a[i].x, b[j].x, acc[i][j]);
                        acc[i][j] = fmaf(a[i].y, b[j].y, acc[i][j]);
                        acc[i][j] = fmaf(a[i].z, b[j].z, acc[i][j]);
                        acc[i][j] = fmaf(a[i].w, b[j].w, acc[i][j]);
                    }
            }
            #pragma unroll
            for (int j = 0; j < 4; j++) {
                int n = c0 + tx + 16 * j;
                float wnv = wn_s[n];
                #pragma unroll
                for (int i = 0; i < 2; i++) {
                    float dist = fmaf(-2.0f, acc[i][j], wnv);
                    if (dist < bvf[i] || (dist == bvf[i] && n < bif[i])) {
                        bvf[i] = dist; bif[i] = n;
                    }
                }
            }
        }

        #pragma unroll
        for (int off = 1; off < 16; off <<= 1) {
            #pragma unroll
            for (int i = 0; i < 2; i++) {
                float ov = __shfl_xor_sync(0xffffffffu, bvf[i], off);
                int   oi = __shfl_xor_sync(0xffffffffu, bif[i], off);
                if (ov < bvf[i] || (ov == bvf[i] && oi < bif[i])) {
                    bvf[i] = ov; bif[i] = oi;
                }
            }
        }
        if (tx == 0) { ri_s[ty] = bif[0]; ri_s[ty + 16] = bif[1]; }
        __syncthreads();

        if (tid < cnt) {
            int nw  = ri_s[tid];
            int old = d_flagidx[base + tid];
            if (nw != old) {
                atomicAdd(&d_counts[nw], 1u);
                atomicSub(&d_counts[old], 1u);
            }
        }
        #pragma unroll
        for (int i = 0; i < 8; i++) {
            int idx = tid + i * 256;
            int s   = idx >> 6;
            int c4  = idx & 63;
            if (s < cnt) {
                int tok = d_flags[base + s];
                int ci  = ri_s[s];
                float4 wv = reinterpret_cast<const float4*>(w + (size_t)ci * E_DIM)[c4];
                reinterpret_cast<float4*>(out + (size_t)tok * E_DIM)[c4] = wv;
            }
        }
    }
}

// =============================================================================
// Kernel 3: perplexity
// =============================================================================
__global__ void vq_perplexity_kernel(float* __restrict__ out_perp) {
    __shared__ float red[N_E];
    int t = threadIdx.x;
    float e = (float)d_counts[t] * (1.0f / (float)N_TOK);
    red[t] = -e * logf(e + 1e-10f);
    __syncthreads();
    #pragma unroll
    for (int s = N_E / 2; s > 0; s >>= 1) {
        if (t < s) red[t] += red[t + s];
        __syncthreads();
    }
    if (t == 0) *out_perp = expf(red[0]);
}

// =============================================================================
extern "C" void kernel_launch(void* const* d_in, const int* in_sizes, int n_in,
                              void* d_out, int out_size) {
    const float* z = (const float*)d_in[0];   // [N_TOK, E_DIM]
    const float* w = (const float*)d_in[1];   // [N_E, E_DIM]
    float* out = (float*)d_out;

    cudaFuncSetAttribute(vq_main_mma,
                         cudaFuncAttributeMaxDynamicSharedMemorySize, SM_TOTAL);
    cudaFuncSetAttribute(vq_fallback,
                         cudaFuncAttributeMaxDynamicSharedMemorySize, FB_SM);

    vq_prep_kernel<<<128, 256>>>(w);
    vq_main_mma<<<N_TOK / TM, THREADS, SM_TOTAL>>>(z, w, out);
    vq_fallback<<<512, 256, FB_SM>>>(z, w, out);
    if (out_size > N_TOK * E_DIM) {
        vq_perplexity_kernel<<<1, N_E>>>(out + (size_t)N_TOK * E_DIM);
    }
}